// round 14
// baseline (speedup 1.0000x reference)
#include <cuda_runtime.h>

// circ_layer: out = mm*x + mm + x, mm[b,i] = sum_j x[b,j] * w[(j-i) mod 1024]
// = circular correlation => IDFT( FFT(x_row) * conj(FFT(w)) ), fp32.
//
// Four-step FFT (1024 = 32x32), one warp per TWO tokens (z = xa + i*xb).
// Complex values in one 64-bit (re,im) pair; butterflies packed f32x2;
// in-FFT rotations scalar with immediate constants (R7 recipe, proven).
// NEW: mid-twiddle and pointwise complex multiplies are packed 2-FMA ops
// using (c,c,s,-s) float4 tables (aligned reg-quad -> zero packing movs),
// and the pointwise table is m-major (coalesced; R7's was 32-line strided).

static constexpr int WPB  = 4;            // warps per block
static constexpr int TPB  = WPB * 32;
static constexpr int NTOK = 65536;

__device__ __align__(16) float2 g_mtw[1024];     // (c,-s), init-internal use
__device__ __align__(16) float4 g_mtwf4[1024];   // fwd mid: (c, c, s, -s), k-major
__device__ __align__(16) float4 g_mtwi4[1024];   // inv mid: (c, c, -s, s), k-major
__device__ __align__(16) float4 g_wc4[1024];     // pointwise: (wr,wr,-wi,wi), m-major

__device__ __forceinline__ int br5(int x) {
    return ((x & 1) << 4) | ((x & 2) << 2) | (x & 4) | ((x & 8) >> 2) | ((x & 16) >> 4);
}

__device__ __forceinline__ float twc(int t) {
    constexpr float C[16] = {
        1.0f,                   0.9807852804032304f,  0.9238795325112867f,  0.8314696123025452f,
        0.7071067811865476f,    0.5555702330196022f,  0.3826834323650898f,  0.1950903220161283f,
        0.0f,                  -0.1950903220161283f, -0.3826834323650898f, -0.5555702330196022f,
       -0.7071067811865476f,   -0.8314696123025452f, -0.9238795325112867f, -0.9807852804032304f };
    return C[t];
}
__device__ __forceinline__ float tws(int t) {
    constexpr float S[16] = {
        0.0f,                   0.1950903220161283f,  0.3826834323650898f,  0.5555702330196022f,
        0.7071067811865476f,    0.8314696123025452f,  0.9238795325112867f,  0.9807852804032304f,
        1.0f,                   0.9807852804032304f,  0.9238795325112867f,  0.8314696123025452f,
        0.7071067811865476f,    0.5555702330196022f,  0.3826834323650898f,  0.1950903220161283f };
    return S[t];
}

// ---------------- packed (re,im) complex in one 64-bit value ----------------

struct P { unsigned long long v; };

__device__ __forceinline__ P pk(float re, float im) {
    P r; asm("mov.b64 %0, {%1, %2};" : "=l"(r.v) : "f"(re), "f"(im)); return r;
}
__device__ __forceinline__ void upk(P a, float& re, float& im) {
    asm("mov.b64 {%0, %1}, %2;" : "=f"(re), "=f"(im) : "l"(a.v));
}
__device__ __forceinline__ P pswap(P a) {               // (im, re): 2 ALU movs
    float r, i; upk(a, r, i); return pk(i, r);
}
__device__ __forceinline__ P padd(P a, P b) {
    P r; asm("add.rn.f32x2 %0, %1, %2;" : "=l"(r.v) : "l"(a.v), "l"(b.v)); return r;
}
__device__ __forceinline__ P pmul(P a, P b) {
    P r; asm("mul.rn.f32x2 %0, %1, %2;" : "=l"(r.v) : "l"(a.v), "l"(b.v)); return r;
}
__device__ __forceinline__ P pfma(P a, P b, P c) {      // a*b + c elementwise
    P r; asm("fma.rn.f32x2 %0, %1, %2, %3;" : "=l"(r.v) : "l"(a.v), "l"(b.v), "l"(c.v)); return r;
}
__device__ __forceinline__ P pneg1() { return pk(-1.0f, -1.0f); }
__device__ __forceinline__ P psub(P a, P b) {           // a - b
    return pfma(b, pneg1(), a);
}
// packed complex multiply with pre-split constant: cc=(c,c), ss encodes +-s
__device__ __forceinline__ P pcmul(P z, P cc, P ss) {
    return pfma(z, cc, pmul(pswap(z), ss));
}

// out = d * e^{-+2*pi*i*t/32}; scalar rotation on unpacked halves (R7 form).
template<bool INV>
__device__ __forceinline__ P prot(int t, P d) {
    if (t == 0) return d;
    float r, i;
    upk(d, r, i);
    if (t == 8) {
        if (!INV) return pk(i, -r);       // * (-i)
        else      return pk(-i, r);       // * (+i)
    }
    const float c = twc(t), s = tws(t);
    if (!INV) return pk(fmaf(r, c,  i * s), fmaf(i, c, -r * s));
    else      return pk(fmaf(r, c, -i * s), fmaf(i, c,  r * s));
}

// DIF radix-2 length-32 FFT: natural in, bit-reversed out.
template<bool INV>
__device__ __forceinline__ void pfft32_dif(P Z[32]) {
#pragma unroll
    for (int s = 0; s < 5; s++) {
        const int len = 32 >> s, half = len >> 1;
#pragma unroll
        for (int g = 0; g < 32; g += len)
#pragma unroll
            for (int j = 0; j < half; j++) {
                const int a = g + j, b = a + half;
                P d = psub(Z[a], Z[b]);
                Z[a] = padd(Z[a], Z[b]);
                Z[b] = prot<INV>(j << s, d);
            }
    }
}

// DIT radix-2 length-32 inverse FFT: bit-reversed in, natural out.
__device__ __forceinline__ void pfft32_dit_inv(P Z[32]) {
#pragma unroll
    for (int s = 4; s >= 0; s--) {
        const int len = 32 >> s, half = len >> 1;
#pragma unroll
        for (int g = 0; g < 32; g += len)
#pragma unroll
            for (int j = 0; j < half; j++) {
                const int a = g + j, b = a + half;
                P t = prot<true>(j << s, Z[b]);
                Z[b] = psub(Z[a], t);
                Z[a] = padd(Z[a], t);
            }
    }
}

// ---------------- scalar FFT (init kernel only) ----------------

template<bool INV>
__device__ __forceinline__ void rot_s(int t, float dr, float di, float& xr, float& xi) {
    if (t == 0)      { xr = dr; xi = di; }
    else if (t == 8) {
        if (!INV) { xr = di;  xi = -dr; }
        else      { xr = -di; xi =  dr; }
    } else {
        float c = twc(t), s = tws(t);
        if (!INV) { xr = fmaf(dr, c,  di * s); xi = fmaf(di, c, -dr * s); }
        else      { xr = fmaf(dr, c, -di * s); xi = fmaf(di, c,  dr * s); }
    }
}
template<bool INV>
__device__ __forceinline__ void fft32_dif_s(float zr[32], float zi[32]) {
#pragma unroll
    for (int s = 0; s < 5; s++) {
        const int len = 32 >> s, half = len >> 1;
#pragma unroll
        for (int g = 0; g < 32; g += len)
#pragma unroll
            for (int j = 0; j < half; j++) {
                const int a = g + j, b = a + half;
                float dr = zr[a] - zr[b], di = zi[a] - zi[b];
                zr[a] += zr[b]; zi[a] += zi[b];
                rot_s<INV>(j << s, dr, di, zr[b], zi[b]);
            }
    }
}

// ---------------- merged init kernel (one block of 1024 threads) ----------------

__global__ void __launch_bounds__(1024) k_init(const float* __restrict__ wv) {
    __shared__ float2 B[32 * 33];
    const int i = threadIdx.x;                       // 0..1023
    {
        int k = i >> 5, lane = i & 31;
        int prod = (k * lane) & 1023;
        float s, c;
        sincospif((float)prod * (1.0f / 512.0f), &s, &c);
        g_mtw[i]   = make_float2(c, -s);             // e^{-2pi*i*k*lane/1024}
        g_mtwf4[i] = make_float4(c, c,  s, -s);      // fwd packed split
        g_mtwi4[i] = make_float4(c, c, -s,  s);      // inv packed split (conj)
    }
    __syncthreads();                                 // g_mtw visible block-wide

    if (i >= 32) return;
    const int lane = i;
    float zr[32], zi[32];
#pragma unroll
    for (int j = 0; j < 32; j++) { zr[j] = wv[32 * j + lane]; zi[j] = 0.0f; }

    fft32_dif_s<false>(zr, zi);                    // over n1; result at br5(k1)
    B[lane * 33 + 0] = make_float2(zr[0], zi[0]);
#pragma unroll
    for (int k1 = 1; k1 < 32; k1++) {              // mid twiddle + transpose store
        const int r = br5(k1);
        float2 t = g_mtw[(k1 << 5) + lane];
        float tr = fmaf(zr[r], t.x, -zi[r] * t.y);
        float ti = fmaf(zi[r], t.x,  zr[r] * t.y);
        B[lane * 33 + k1] = make_float2(tr, ti);
    }
    __syncwarp();
#pragma unroll
    for (int n2 = 0; n2 < 32; n2++) {
        float2 v = B[n2 * 33 + lane];
        zr[n2] = v.x; zi[n2] = v.y;
    }
    fft32_dif_s<false>(zr, zi);                    // over n2; result at br5(k2)
    // Wc = conj(FFT(w))/N as packed-split, M-MAJOR (coalesced in main):
    // value m of lane holds (wr, wr, -wi, wi)
#pragma unroll
    for (int m = 0; m < 32; m++) {
        float wr =  zr[m] * (1.0f / 1024.0f);
        float wi = -zi[m] * (1.0f / 1024.0f);
        g_wc4[m * 32 + lane] = make_float4(wr, wr, -wi, wi);
    }
}

// ---------------- main kernel ----------------

__global__ void __launch_bounds__(TPB, 3) k_main(const float* __restrict__ x,
                                                 float* __restrict__ out) {
    __shared__ unsigned long long tb[WPB][32 * 33];   // per-warp (re,im) plane
    const int lane = threadIdx.x & 31;
    const int wid  = threadIdx.x >> 5;
    unsigned long long* B = tb[wid];

    const long base = ((long)blockIdx.x * WPB + wid) * 2048;   // 2 tokens
    const float* __restrict__ xa = x + base;
    const float* __restrict__ xb = xa + 1024;

    P Z[32];
#pragma unroll
    for (int i = 0; i < 32; i++)                   // coalesced 128B per ld
        Z[i] = pk(xa[32 * i + lane], xb[32 * i + lane]);

    // ---- forward: FFT over n1, mid twiddle + transpose, FFT over n2 ----
    pfft32_dif<false>(Z);                          // result at br5(k1)

    B[lane * 33 + 0] = Z[0].v;
#pragma unroll
    for (int k1 = 1; k1 < 32; k1++) {              // * e^{-2pi*i*lane*k1/1024}
        const int r = br5(k1);
        float4 t = g_mtwf4[(k1 << 5) + lane];      // (c, c, s, -s), coalesced
        B[lane * 33 + k1] = pcmul(Z[r], pk(t.x, t.y), pk(t.z, t.w)).v;
    }
    __syncwarp();
#pragma unroll
    for (int n2 = 0; n2 < 32; n2++)                // transpose: lane := k1
        Z[n2].v = B[n2 * 33 + lane];
    pfft32_dif<false>(Z);                          // over n2; at br5(k2)

    // ---- pointwise: Z * conj(W)/N (m-major table, coalesced, packed) ----
#pragma unroll
    for (int m = 0; m < 32; m++) {
        float4 v = g_wc4[m * 32 + lane];           // (wr, wr, -wi, wi)
        Z[m] = pcmul(Z[m], pk(v.x, v.y), pk(v.z, v.w));
    }

    // ---- inverse: IFFT over k2, conj mid twiddle + transpose, IFFT over k1 ----
    pfft32_dit_inv(Z);                             // br in -> natural n2

    __syncwarp();                                  // transpose-1 loads done
    B[lane * 33 + 0] = Z[0].v;
#pragma unroll
    for (int n2 = 1; n2 < 32; n2++) {              // * e^{+2pi*i*n2*lane/1024}
        float4 t = g_mtwi4[(n2 << 5) + lane];      // (c, c, -s, s)
        B[lane * 33 + n2] = pcmul(Z[n2], pk(t.x, t.y), pk(t.z, t.w)).v;
    }
    __syncwarp();
#pragma unroll
    for (int k1 = 0; k1 < 32; k1++)                // transpose: lane := n2
        Z[k1].v = B[k1 * 33 + lane];
    pfft32_dif<true>(Z);                           // inverse over k1 -> br5(n1)

    // ---- epilogue: mm at (lane=n2, reg br5(n1)) => token index 32*n1+lane ----
    float* __restrict__ oa = out + base;
    float* __restrict__ ob = oa + 1024;
#pragma unroll
    for (int n1 = 0; n1 < 32; n1++) {
        const int r = br5(n1);
        const int idx = 32 * n1 + lane;
        P px = pk(xa[idx], xb[idx]);               // reload (L1-hot)
        P o  = pfma(Z[r], px, padd(Z[r], px));     // mm*x + (mm + x), packed
        float o1, o2;
        upk(o, o1, o2);
        oa[idx] = o1;
        ob[idx] = o2;
    }
}

extern "C" void kernel_launch(void* const* d_in, const int* in_sizes, int n_in,
                              void* d_out, int out_size) {
    const float* x = (const float*)d_in[0];   // [65536, 1024] fp32
    const float* w = (const float*)d_in[1];   // [1024] fp32
    float* out = (float*)d_out;

    k_init<<<1, 1024>>>(w);
    k_main<<<NTOK / 2 / WPB, TPB>>>(x, out);
}

// round 15
// speedup vs baseline: 1.6125x; 1.6125x over previous
#include <cuda_runtime.h>

// circ_layer: out = mm*x + mm + x, mm[b,i] = sum_j x[b,j] * w[(j-i) mod 1024]
// = circular correlation => IDFT( FFT(x_row) * conj(FFT(w)) ), fp32.
//
// Four-step FFT (1024 = 32x32), one warp per TWO tokens (z = xa + i*xb).
// Each complex value lives in ONE 64-bit register pair (re,im); butterfly
// add/sub use packed add/fma.rn.f32x2 (half the instructions), rotations
// unpack to scalars (immediate-constant FMAs) and repack — the proven R7
// recipe, byte-exact. This round's only deltas vs R7:
//   (1) pointwise table g_wc2 is M-MAJOR [m*32+lane] -> coalesced LDG.64
//       (R7's layout made each float4 load touch 32 L1 lines), same math;
//   (2) merged single init kernel.

static constexpr int WPB  = 4;            // warps per block
static constexpr int TPB  = WPB * 32;
static constexpr int NTOK = 65536;

__device__ __align__(16) float2 g_wc2[1024];   // conj(FFT(w))/N, (wr,wi), M-MAJOR
__device__ __align__(16) float2 g_mtw[1024];   // T[k*32+lane] = e^{-2pi*i*k*lane/1024}

__device__ __forceinline__ int br5(int x) {
    return ((x & 1) << 4) | ((x & 2) << 2) | (x & 4) | ((x & 8) >> 2) | ((x & 16) >> 4);
}

__device__ __forceinline__ float twc(int t) {
    constexpr float C[16] = {
        1.0f,                   0.9807852804032304f,  0.9238795325112867f,  0.8314696123025452f,
        0.7071067811865476f,    0.5555702330196022f,  0.3826834323650898f,  0.1950903220161283f,
        0.0f,                  -0.1950903220161283f, -0.3826834323650898f, -0.5555702330196022f,
       -0.7071067811865476f,   -0.8314696123025452f, -0.9238795325112867f, -0.9807852804032304f };
    return C[t];
}
__device__ __forceinline__ float tws(int t) {
    constexpr float S[16] = {
        0.0f,                   0.1950903220161283f,  0.3826834323650898f,  0.5555702330196022f,
        0.7071067811865476f,    0.8314696123025452f,  0.9238795325112867f,  0.9807852804032304f,
        1.0f,                   0.9807852804032304f,  0.9238795325112867f,  0.8314696123025452f,
        0.7071067811865476f,    0.5555702330196022f,  0.3826834323650898f,  0.1950903220161283f };
    return S[t];
}

// ---------------- packed (re,im) complex in one 64-bit value ----------------

struct P { unsigned long long v; };

__device__ __forceinline__ P pk(float re, float im) {
    P r; asm("mov.b64 %0, {%1, %2};" : "=l"(r.v) : "f"(re), "f"(im)); return r;
}
__device__ __forceinline__ void upk(P a, float& re, float& im) {
    asm("mov.b64 {%0, %1}, %2;" : "=f"(re), "=f"(im) : "l"(a.v));
}
__device__ __forceinline__ P padd(P a, P b) {           // complex add (2 lanes)
    P r; asm("add.rn.f32x2 %0, %1, %2;" : "=l"(r.v) : "l"(a.v), "l"(b.v)); return r;
}
__device__ __forceinline__ P pfma(P a, P b, P c) {      // a*b + c elementwise
    P r; asm("fma.rn.f32x2 %0, %1, %2, %3;" : "=l"(r.v) : "l"(a.v), "l"(b.v), "l"(c.v)); return r;
}
__device__ __forceinline__ P pneg1() {                  // (-1, -1); CSE'd by ptxas
    return pk(-1.0f, -1.0f);
}
__device__ __forceinline__ P psub(P a, P b) {           // a - b  (b*-1 + a)
    return pfma(b, pneg1(), a);
}

// out = d * e^{-+2*pi*i*t/32}; scalar rotation on unpacked halves.
template<bool INV>
__device__ __forceinline__ P prot(int t, P d) {
    if (t == 0) return d;
    float r, i;
    upk(d, r, i);
    if (t == 8) {
        if (!INV) return pk(i, -r);       // * (-i)
        else      return pk(-i, r);       // * (+i)
    }
    const float c = twc(t), s = tws(t);
    if (!INV) return pk(fmaf(r, c,  i * s), fmaf(i, c, -r * s));
    else      return pk(fmaf(r, c, -i * s), fmaf(i, c,  r * s));
}

// DIF radix-2 length-32 FFT: natural in, bit-reversed out.
template<bool INV>
__device__ __forceinline__ void pfft32_dif(P Z[32]) {
#pragma unroll
    for (int s = 0; s < 5; s++) {
        const int len = 32 >> s, half = len >> 1;
#pragma unroll
        for (int g = 0; g < 32; g += len)
#pragma unroll
            for (int j = 0; j < half; j++) {
                const int a = g + j, b = a + half;
                P d = psub(Z[a], Z[b]);
                Z[a] = padd(Z[a], Z[b]);
                Z[b] = prot<INV>(j << s, d);
            }
    }
}

// DIT radix-2 length-32 inverse FFT: bit-reversed in, natural out.
__device__ __forceinline__ void pfft32_dit_inv(P Z[32]) {
#pragma unroll
    for (int s = 4; s >= 0; s--) {
        const int len = 32 >> s, half = len >> 1;
#pragma unroll
        for (int g = 0; g < 32; g += len)
#pragma unroll
            for (int j = 0; j < half; j++) {
                const int a = g + j, b = a + half;
                P t = prot<true>(j << s, Z[b]);
                Z[b] = psub(Z[a], t);
                Z[a] = padd(Z[a], t);
            }
    }
}

// ---------------- scalar FFT (init kernel only) ----------------

template<bool INV>
__device__ __forceinline__ void rot_s(int t, float dr, float di, float& xr, float& xi) {
    if (t == 0)      { xr = dr; xi = di; }
    else if (t == 8) {
        if (!INV) { xr = di;  xi = -dr; }
        else      { xr = -di; xi =  dr; }
    } else {
        float c = twc(t), s = tws(t);
        if (!INV) { xr = fmaf(dr, c,  di * s); xi = fmaf(di, c, -dr * s); }
        else      { xr = fmaf(dr, c, -di * s); xi = fmaf(di, c,  dr * s); }
    }
}
template<bool INV>
__device__ __forceinline__ void fft32_dif_s(float zr[32], float zi[32]) {
#pragma unroll
    for (int s = 0; s < 5; s++) {
        const int len = 32 >> s, half = len >> 1;
#pragma unroll
        for (int g = 0; g < 32; g += len)
#pragma unroll
            for (int j = 0; j < half; j++) {
                const int a = g + j, b = a + half;
                float dr = zr[a] - zr[b], di = zi[a] - zi[b];
                zr[a] += zr[b]; zi[a] += zi[b];
                rot_s<INV>(j << s, dr, di, zr[b], zi[b]);
            }
    }
}

// ---------------- merged init kernel (one block of 1024 threads) ----------------
// Phase 1: all threads fill g_mtw. Phase 2 (after __syncthreads): warp 0
// computes Wc = conj(FFT(w))/N via the scalar four-step pipeline.

__global__ void __launch_bounds__(1024) k_init(const float* __restrict__ wv) {
    __shared__ float2 B[32 * 33];
    const int i = threadIdx.x;                       // 0..1023
    {
        int k = i >> 5, lane = i & 31;
        int prod = (k * lane) & 1023;
        float s, c;
        sincospif((float)prod * (1.0f / 512.0f), &s, &c);
        g_mtw[i] = make_float2(c, -s);               // e^{-2pi*i*k*lane/1024}
    }
    __syncthreads();                                 // g_mtw visible block-wide

    if (i >= 32) return;
    const int lane = i;
    float zr[32], zi[32];
#pragma unroll
    for (int j = 0; j < 32; j++) { zr[j] = wv[32 * j + lane]; zi[j] = 0.0f; }

    fft32_dif_s<false>(zr, zi);                    // over n1; result at br5(k1)
    B[lane * 33 + 0] = make_float2(zr[0], zi[0]);
#pragma unroll
    for (int k1 = 1; k1 < 32; k1++) {              // mid twiddle + transpose store
        const int r = br5(k1);
        float2 t = g_mtw[(k1 << 5) + lane];
        float tr = fmaf(zr[r], t.x, -zi[r] * t.y);
        float ti = fmaf(zi[r], t.x,  zr[r] * t.y);
        B[lane * 33 + k1] = make_float2(tr, ti);
    }
    __syncwarp();
#pragma unroll
    for (int n2 = 0; n2 < 32; n2++) {
        float2 v = B[n2 * 33 + lane];
        zr[n2] = v.x; zi[n2] = v.y;
    }
    fft32_dif_s<false>(zr, zi);                    // over n2; result at br5(k2)
    // Wc = conj(FFT(w))/N, M-MAJOR layout [m*32 + lane] -> coalesced in k_main
#pragma unroll
    for (int m = 0; m < 32; m++)
        g_wc2[m * 32 + lane] = make_float2(zr[m] * (1.0f / 1024.0f),
                                           zi[m] * (-1.0f / 1024.0f));
}

// ---------------- main kernel ----------------

__global__ void __launch_bounds__(TPB, 3) k_main(const float* __restrict__ x,
                                                 float* __restrict__ out) {
    __shared__ unsigned long long tb[WPB][32 * 33];   // per-warp (re,im) plane
    const int lane = threadIdx.x & 31;
    const int wid  = threadIdx.x >> 5;
    unsigned long long* B = tb[wid];

    const long base = ((long)blockIdx.x * WPB + wid) * 2048;   // 2 tokens
    const float* __restrict__ xa = x + base;
    const float* __restrict__ xb = xa + 1024;

    P Z[32];
#pragma unroll
    for (int i = 0; i < 32; i++)                   // coalesced 128B per ld
        Z[i] = pk(xa[32 * i + lane], xb[32 * i + lane]);

    // ---- forward: FFT over n1, mid twiddle + transpose, FFT over n2 ----
    pfft32_dif<false>(Z);                          // result at br5(k1)

    B[lane * 33 + 0] = Z[0].v;
#pragma unroll
    for (int k1 = 1; k1 < 32; k1++) {              // * e^{-2pi*i*lane*k1/1024}
        const int r = br5(k1);
        float2 t = g_mtw[(k1 << 5) + lane];        // (c, -s), coalesced
        float zr, zi;
        upk(Z[r], zr, zi);
        float tr = fmaf(zr, t.x, -zi * t.y);
        float ti = fmaf(zi, t.x,  zr * t.y);
        B[lane * 33 + k1] = pk(tr, ti).v;
    }
    __syncwarp();
#pragma unroll
    for (int n2 = 0; n2 < 32; n2++)                // transpose: lane := k1
        Z[n2].v = B[n2 * 33 + lane];
    pfft32_dif<false>(Z);                          // over n2; at br5(k2)

    // ---- pointwise: Z * conj(W)/N (m-major table -> coalesced LDG.64) ----
#pragma unroll
    for (int m = 0; m < 32; m++) {
        float2 v = g_wc2[m * 32 + lane];           // (wr, wi)
        float a, b;
        upk(Z[m], a, b);
        Z[m] = pk(fmaf(a, v.x, -b * v.y), fmaf(a, v.y, b * v.x));
    }

    // ---- inverse: IFFT over k2, conj mid twiddle + transpose, IFFT over k1 ----
    pfft32_dit_inv(Z);                             // br in -> natural n2

    __syncwarp();                                  // transpose-1 loads done
    B[lane * 33 + 0] = Z[0].v;
#pragma unroll
    for (int n2 = 1; n2 < 32; n2++) {              // * e^{+2pi*i*n2*lane/1024}
        float2 t = g_mtw[(n2 << 5) + lane];        // conj of (c,-s)
        float zr, zi;
        upk(Z[n2], zr, zi);
        float tr = fmaf(zr, t.x,  zi * t.y);
        float ti = fmaf(zi, t.x, -zr * t.y);
        B[lane * 33 + n2] = pk(tr, ti).v;
    }
    __syncwarp();
#pragma unroll
    for (int k1 = 0; k1 < 32; k1++)                // transpose: lane := n2
        Z[k1].v = B[k1 * 33 + lane];
    pfft32_dif<true>(Z);                           // inverse over k1 -> br5(n1)

    // ---- epilogue: mm at (lane=n2, reg br5(n1)) => token index 32*n1+lane ----
    float* __restrict__ oa = out + base;
    float* __restrict__ ob = oa + 1024;
#pragma unroll
    for (int n1 = 0; n1 < 32; n1++) {
        const int r = br5(n1);
        const int idx = 32 * n1 + lane;
        float ma, mb;
        upk(Z[r], ma, mb);
        float xav = xa[idx], xbv = xb[idx];        // reload (L1-hot)
        oa[idx] = fmaf(ma, xav, ma + xav);         // mm*x + mm + x
        ob[idx] = fmaf(mb, xbv, mb + xbv);
    }
}

extern "C" void kernel_launch(void* const* d_in, const int* in_sizes, int n_in,
                              void* d_out, int out_size) {
    const float* x = (const float*)d_in[0];   // [65536, 1024] fp32
    const float* w = (const float*)d_in[1];   // [1024] fp32
    float* out = (float*)d_out;

    k_init<<<1, 1024>>>(w);
    k_main<<<NTOK / 2 / WPB, TPB>>>(x, out);
}